// round 3
// baseline (speedup 1.0000x reference)
#include <cuda_runtime.h>

// Fused DepthwiseSeparableConv3d: depthwise 3x3x3 (SAME) + bias + BN + ReLU,
// then pointwise 64->128 GEMM + bias + BN + ReLU.
// B=2, D=H=W=48, C=64, F=128. fp32, packed f32x2 FMA in BOTH stages.
// R3: two-pass GEMM (f-sub-tile 8 per pass) keeps accum regs at 24 so we hold
// 3 CTAs/SM; broadcast weight LDS + per-lane conflict-free y LDS.

#define NB   2
#define ND   48
#define NC   64
#define NF   128
#define SYS  98   // sY row stride (even for aligned float2, conflict-free)

__device__ __forceinline__ unsigned long long dup2(float v) {
    unsigned long long r;
    unsigned u = __float_as_uint(v);
    asm("mov.b64 %0, {%1, %1};" : "=l"(r) : "r"(u));
    return r;
}

__device__ __forceinline__ unsigned long long pack2(float a, float b) {
    unsigned long long r;
    asm("mov.b64 %0, {%1, %2};" : "=l"(r)
        : "r"(__float_as_uint(a)), "r"(__float_as_uint(b)));
    return r;
}

__device__ __forceinline__ void fma2(unsigned long long& d,
                                     unsigned long long a,
                                     unsigned long long b) {
    asm("fma.rn.f32x2 %0, %1, %2, %0;" : "+l"(d) : "l"(a), "l"(b));
}

__device__ __forceinline__ float lo32(unsigned long long v) {
    return __uint_as_float((unsigned)(v & 0xffffffffull));
}
__device__ __forceinline__ float hi32(unsigned long long v) {
    return __uint_as_float((unsigned)(v >> 32));
}

__global__ __launch_bounds__(256, 3)
void dwsep3d_fused_kernel(
    const float* __restrict__ x,
    const float* __restrict__ dwk,   // (3,3,3,1,C)
    const float* __restrict__ dwb,   // (C)
    const float* __restrict__ g1, const float* __restrict__ b1,
    const float* __restrict__ m1, const float* __restrict__ v1,
    const float* __restrict__ pw,    // (C,F)
    const float* __restrict__ pb,    // (F)
    const float* __restrict__ g2, const float* __restrict__ b2,
    const float* __restrict__ m2, const float* __restrict__ v2,
    float* __restrict__ out)
{
    __shared__ float sW[NC * NF];      // 32768 B, pointwise weights [c][f]
    __shared__ float sY[NC * SYS];     // 25088 B, stage-1 result [c][widx 0..95]
    __shared__ float sS1[NC], sT1[NC];
    __shared__ float sS2[NF], sT2[NF];

    const int tid = threadIdx.x;
    const int bid = blockIdx.x;            // 0 .. B*D*24-1
    const int h0 = (bid % 24) * 2;         // pair of h rows
    const int d  = (bid / 24) % ND;
    const int b  = bid / (24 * ND);

    // ---- stage 0: stage pointwise weights + fold BN params -------------------
    {
        const float4* src = (const float4*)pw;
        float4* dst = (float4*)sW;
        #pragma unroll
        for (int i = tid; i < NC * NF / 4; i += 256) dst[i] = src[i];
    }
    if (tid < NC) {
        const int c = tid;
        float inv = g1[c] * rsqrtf(v1[c] + 1e-3f);
        sS1[c] = inv;
        sT1[c] = dwb[c] * inv + b1[c] - m1[c] * inv;   // folds dw bias + BN1
    } else if (tid < NC + NF) {
        const int f = tid - NC;
        float inv = g2[f] * rsqrtf(v2[f] + 1e-3f);
        sS2[f] = inv;
        sT2[f] = pb[f] * inv + b2[f] - m2[f] * inv;    // folds pw bias + BN2
    }
    __syncthreads();

    // ---- stage 1: depthwise 3x3x3 + BN1 + ReLU -> sY[c][widx], f32x2 ---------
    {
        const int c  = tid & 63;           // channel
        const int wg = tid >> 6;           // 0..3 -> w range [wg*12, wg*12+12)
        const int w0 = wg * 12;
        const float s1v = sS1[c], t1v = sT1[c];
        const unsigned long long s1d = dup2(s1v);
        const unsigned long long t1d = dup2(t1v);

        #pragma unroll
        for (int hr = 0; hr < 2; hr++) {
            const int h = h0 + hr;
            unsigned long long acc[6];     // w-pairs (w0+2j, w0+2j+1)
            #pragma unroll
            for (int j = 0; j < 6; j++) acc[j] = 0ull;

            #pragma unroll
            for (int dd = 0; dd < 3; dd++) {
                const int zd = d + dd - 1;
                if (zd < 0 || zd >= ND) continue;
                #pragma unroll
                for (int hh = 0; hh < 3; hh++) {
                    const int zh = h + hh - 1;
                    if (zh < 0 || zh >= ND) continue;
                    const float* xb =
                        x + (((size_t)((b * ND + zd) * ND + zh)) * ND) * NC + c;
                    float xv[14];
                    #pragma unroll
                    for (int j = 0; j < 14; j++) {
                        const int wx = w0 - 1 + j;
                        xv[j] = (wx >= 0 && wx < ND) ? __ldg(xb + wx * NC) : 0.f;
                    }
                    unsigned long long P[13];
                    #pragma unroll
                    for (int i = 0; i < 13; i++) P[i] = pack2(xv[i], xv[i + 1]);
                    const int kb = ((dd * 3 + hh) * 3) * NC + c;
                    const unsigned long long k0 = dup2(__ldg(dwk + kb));
                    const unsigned long long k1 = dup2(__ldg(dwk + kb + NC));
                    const unsigned long long k2 = dup2(__ldg(dwk + kb + 2 * NC));
                    #pragma unroll
                    for (int j = 0; j < 6; j++) {
                        fma2(acc[j], P[2 * j],     k0);
                        fma2(acc[j], P[2 * j + 1], k1);
                        fma2(acc[j], P[2 * j + 2], k2);
                    }
                }
            }
            float2* yrow = (float2*)&sY[c * SYS + hr * 48 + w0];
            #pragma unroll
            for (int j = 0; j < 6; j++) {
                unsigned long long z = acc[j];
                fma2(z, s1d, t1d);   // wrong order? fma2(d,a,b): d = a*b+d
                // we need acc*s1 + t1: compute via temp
                float2 o;
                o.x = fmaxf(fmaf(lo32(acc[j]), s1v, t1v), 0.f);
                o.y = fmaxf(fmaf(hi32(acc[j]), s1v, t1v), 0.f);
                yrow[j] = o;
            }
        }
    }
    __syncthreads();

    // ---- stage 2: GEMM z[96][128] = y[96][64] @ W[64][128], two passes -------
    // warp: f-tile 16 split into 2 sub-tiles of 8 (broadcast weight LDS);
    // lane: w = lane + 32p (conflict-free y LDS).
    {
        const int lane = tid & 31;
        const int wid  = tid >> 5;         // 0..7
        const int fbase = wid * 16;
        float* ob0 = out + (((size_t)((b * ND + d) * ND + h0)) * ND) * NF;

        #pragma unroll
        for (int pass = 0; pass < 2; pass++) {
            const int f0 = fbase + pass * 8;

            unsigned long long acc[3][4];  // [p][f-pair]
            #pragma unroll
            for (int p = 0; p < 3; p++)
                #pragma unroll
                for (int q = 0; q < 4; q++) acc[p][q] = 0ull;

            #pragma unroll 4
            for (int c = 0; c < NC; c++) {
                const ulonglong2* wp = (const ulonglong2*)&sW[c * NF + f0];
                const ulonglong2 wA = wp[0];   // f-pairs q=0,1
                const ulonglong2 wB = wp[1];   // q=2,3
                const float* yr = &sY[c * SYS + lane];
                const unsigned long long y0 = dup2(yr[0]);
                const unsigned long long y1 = dup2(yr[32]);
                const unsigned long long y2 = dup2(yr[64]);

                fma2(acc[0][0], y0, wA.x); fma2(acc[0][1], y0, wA.y);
                fma2(acc[0][2], y0, wB.x); fma2(acc[0][3], y0, wB.y);
                fma2(acc[1][0], y1, wA.x); fma2(acc[1][1], y1, wA.y);
                fma2(acc[1][2], y1, wB.x); fma2(acc[1][3], y1, wB.y);
                fma2(acc[2][0], y2, wA.x); fma2(acc[2][1], y2, wA.y);
                fma2(acc[2][2], y2, wB.x); fma2(acc[2][3], y2, wB.y);
            }

            // epilogue: BN2 + ReLU; per lane 8 consecutive f = 32B (one sector)
            float s2[8], t2[8];
            #pragma unroll
            for (int q = 0; q < 2; q++) {
                *(float4*)&s2[q * 4] = *(const float4*)&sS2[f0 + q * 4];
                *(float4*)&t2[q * 4] = *(const float4*)&sT2[f0 + q * 4];
            }
            #pragma unroll
            for (int p = 0; p < 3; p++) {
                float z[8];
                #pragma unroll
                for (int q = 0; q < 4; q++) {
                    z[2 * q]     = fmaxf(fmaf(lo32(acc[p][q]), s2[2 * q],     t2[2 * q]),     0.f);
                    z[2 * q + 1] = fmaxf(fmaf(hi32(acc[p][q]), s2[2 * q + 1], t2[2 * q + 1]), 0.f);
                }
                float* op = ob0 + (size_t)(lane + 32 * p) * NF + f0;
                *(float4*)&op[0] = *(float4*)&z[0];
                *(float4*)&op[4] = *(float4*)&z[4];
            }
        }
    }
}

extern "C" void kernel_launch(void* const* d_in, const int* in_sizes, int n_in,
                              void* d_out, int out_size) {
    const float* x   = (const float*)d_in[0];
    const float* dwk = (const float*)d_in[1];
    const float* dwb = (const float*)d_in[2];
    const float* g1  = (const float*)d_in[3];
    const float* b1  = (const float*)d_in[4];
    const float* m1  = (const float*)d_in[5];
    const float* v1  = (const float*)d_in[6];
    const float* pw  = (const float*)d_in[7];
    const float* pb  = (const float*)d_in[8];
    const float* g2  = (const float*)d_in[9];
    const float* b2  = (const float*)d_in[10];
    const float* m2  = (const float*)d_in[11];
    const float* v2  = (const float*)d_in[12];
    float* out = (float*)d_out;

    dim3 grid(NB * ND * 24);   // 2304 blocks: one (b,d,h-pair) -> 96 w each
    dim3 block(256);
    dwsep3d_fused_kernel<<<grid, block>>>(x, dwk, dwb, g1, b1, m1, v1,
                                          pw, pb, g2, b2, m2, v2, out);
}

// round 4
// speedup vs baseline: 1.1944x; 1.1944x over previous
#include <cuda_runtime.h>

// Fused DepthwiseSeparableConv3d: depthwise 3x3x3 (SAME) + bias + BN + ReLU,
// then pointwise 64->128 GEMM + bias + BN + ReLU.
// B=2, D=H=W=48, C=64, F=128. fp32, packed f32x2 everywhere.
// R4: stage-1 vectorizes over channel-PAIRS (native float2 LDG, no packing);
// GEMM warp tile = 8w x 128f: y read as two 16B broadcast LDS (u64 pairs),
// weights spread LDS.128; 6 LDS phases per 16 fma2 -> fma-pipe bound.

#define NB   2
#define ND   48
#define NC   64
#define NF   128
#define SYS  52   // sY row stride (mult of 4 -> 16B-aligned 8w groups)

__device__ __forceinline__ unsigned long long dup2(float v) {
    unsigned long long r;
    unsigned u = __float_as_uint(v);
    asm("mov.b64 %0, {%1, %1};" : "=l"(r) : "r"(u));
    return r;
}

__device__ __forceinline__ void fma2(unsigned long long& d,
                                     unsigned long long a,
                                     unsigned long long b) {
    asm("fma.rn.f32x2 %0, %1, %2, %0;" : "+l"(d) : "l"(a), "l"(b));
}

__device__ __forceinline__ float lo32(unsigned long long v) {
    return __uint_as_float((unsigned)(v & 0xffffffffull));
}
__device__ __forceinline__ float hi32(unsigned long long v) {
    return __uint_as_float((unsigned)(v >> 32));
}

__device__ __forceinline__ unsigned long long f2u(float2 v) {
    unsigned long long r;
    asm("mov.b64 %0, {%1, %2};" : "=l"(r)
        : "r"(__float_as_uint(v.x)), "r"(__float_as_uint(v.y)));
    return r;
}

__global__ __launch_bounds__(192, 4)
void dwsep3d_fused_kernel(
    const float* __restrict__ x,
    const float* __restrict__ dwk,   // (3,3,3,1,C)
    const float* __restrict__ dwb,   // (C)
    const float* __restrict__ g1, const float* __restrict__ b1,
    const float* __restrict__ m1, const float* __restrict__ v1,
    const float* __restrict__ pw,    // (C,F)
    const float* __restrict__ pb,    // (F)
    const float* __restrict__ g2, const float* __restrict__ b2,
    const float* __restrict__ m2, const float* __restrict__ v2,
    float* __restrict__ out)
{
    __shared__ float sW[NC * NF];      // 32768 B, pointwise weights [c][f]
    __shared__ float sY[NC * SYS];     // 13312 B, stage-1 result [c][w]
    __shared__ float sS1[NC], sT1[NC];
    __shared__ float sS2[NF], sT2[NF];

    const int tid = threadIdx.x;
    const int bid = blockIdx.x;            // 0 .. B*D*H-1
    const int h = bid % ND;
    const int d = (bid / ND) % ND;
    const int b = bid / (ND * ND);

    // ---- stage 0: stage pointwise weights + fold BN params -------------------
    {
        const float4* src = (const float4*)pw;
        float4* dst = (float4*)sW;
        #pragma unroll
        for (int i = tid; i < NC * NF / 4; i += 192) dst[i] = src[i];
    }
    if (tid < NC) {
        const int c = tid;
        float inv = g1[c] * rsqrtf(v1[c] + 1e-3f);
        sS1[c] = inv;
        sT1[c] = dwb[c] * inv + b1[c] - m1[c] * inv;   // folds dw bias + BN1
    } else if (tid < NC + NF) {
        const int f = tid - NC;
        float inv = g2[f] * rsqrtf(v2[f] + 1e-3f);
        sS2[f] = inv;
        sT2[f] = pb[f] * inv + b2[f] - m2[f] * inv;    // folds pw bias + BN2
    }
    __syncthreads();

    // ---- stage 1: depthwise 3x3x3 + BN1 + ReLU, f32x2 over channel pairs ----
    // thread = (cpair = tid&31 -> channels 2cp,2cp+1 ; wseg = tid>>5 -> 8 w)
    {
        const int c0 = (tid & 31) * 2;
        const int w0 = (tid >> 5) * 8;

        unsigned long long acc[8];         // acc[w] = (y[c0], y[c1]) partials
        #pragma unroll
        for (int j = 0; j < 8; j++) acc[j] = 0ull;

        #pragma unroll
        for (int dd = 0; dd < 3; dd++) {
            const int zd = d + dd - 1;
            if (zd < 0 || zd >= ND) continue;
            #pragma unroll
            for (int hh = 0; hh < 3; hh++) {
                const int zh = h + hh - 1;
                if (zh < 0 || zh >= ND) continue;
                const float* xb =
                    x + (((size_t)((b * ND + zd) * ND + zh)) * ND) * NC + c0;
                unsigned long long xv[10];  // window w0-1 .. w0+8, c-pairs
                #pragma unroll
                for (int j = 0; j < 10; j++) {
                    const int wx = w0 - 1 + j;
                    xv[j] = (wx >= 0 && wx < ND)
                        ? f2u(__ldg((const float2*)(xb + wx * NC))) : 0ull;
                }
                const float* kb = dwk + ((dd * 3 + hh) * 3) * NC + c0;
                const unsigned long long k0 = f2u(__ldg((const float2*)kb));
                const unsigned long long k1 = f2u(__ldg((const float2*)(kb + NC)));
                const unsigned long long k2 = f2u(__ldg((const float2*)(kb + 2 * NC)));
                #pragma unroll
                for (int j = 0; j < 8; j++) {
                    fma2(acc[j], xv[j],     k0);
                    fma2(acc[j], xv[j + 1], k1);
                    fma2(acc[j], xv[j + 2], k2);
                }
            }
        }
        // BN1 + ReLU (f32x2 for the affine), scatter to sY[c][w]
        const unsigned long long s1p = f2u(*(const float2*)&sS1[c0]);
        const unsigned long long t1p = f2u(*(const float2*)&sT1[c0]);
        #pragma unroll
        for (int j = 0; j < 8; j++) {
            unsigned long long z = t1p;
            fma2(z, acc[j], s1p);          // z = acc*s1 + t1
            sY[c0 * SYS + w0 + j]       = fmaxf(lo32(z), 0.f);
            sY[(c0 + 1) * SYS + w0 + j] = fmaxf(hi32(z), 0.f);
        }
    }
    __syncthreads();

    // ---- stage 2: GEMM z[48][128] = y[48][64] @ W[64][128] -------------------
    // warp tile: 8 w (uniform) x 128 f (lanes, 4 each). y = 2 broadcast 16B LDS.
    {
        const int lane = tid & 31;
        const int wid  = tid >> 5;         // 0..5
        const int f0   = lane * 4;
        const int w0   = wid * 8;

        unsigned long long acc[4][4];      // [w-pair][f]
        #pragma unroll
        for (int p = 0; p < 4; p++)
            #pragma unroll
            for (int q = 0; q < 4; q++) acc[p][q] = 0ull;

        #pragma unroll 4
        for (int c = 0; c < NC; c++) {
            const float4 wv = *(const float4*)&sW[c * NF + f0];
            const unsigned long long wd0 = dup2(wv.x);
            const unsigned long long wd1 = dup2(wv.y);
            const unsigned long long wd2 = dup2(wv.z);
            const unsigned long long wd3 = dup2(wv.w);
            const ulonglong2 ya = *(const ulonglong2*)&sY[c * SYS + w0];
            const ulonglong2 yb = *(const ulonglong2*)&sY[c * SYS + w0 + 4];

            fma2(acc[0][0], ya.x, wd0); fma2(acc[0][1], ya.x, wd1);
            fma2(acc[0][2], ya.x, wd2); fma2(acc[0][3], ya.x, wd3);
            fma2(acc[1][0], ya.y, wd0); fma2(acc[1][1], ya.y, wd1);
            fma2(acc[1][2], ya.y, wd2); fma2(acc[1][3], ya.y, wd3);
            fma2(acc[2][0], yb.x, wd0); fma2(acc[2][1], yb.x, wd1);
            fma2(acc[2][2], yb.x, wd2); fma2(acc[2][3], yb.x, wd3);
            fma2(acc[3][0], yb.y, wd0); fma2(acc[3][1], yb.y, wd1);
            fma2(acc[3][2], yb.y, wd2); fma2(acc[3][3], yb.y, wd3);
        }

        // epilogue: BN2 + ReLU; per w a full warp writes 512B contiguous.
        const float4 s2 = *(const float4*)&sS2[f0];
        const float4 t2 = *(const float4*)&sT2[f0];
        float* ob = out + (((size_t)((b * ND + d) * ND + h)) * ND + w0) * NF + f0;

        #pragma unroll
        for (int p = 0; p < 4; p++) {
            float4 o0, o1;
            o0.x = fmaxf(fmaf(lo32(acc[p][0]), s2.x, t2.x), 0.f);
            o0.y = fmaxf(fmaf(lo32(acc[p][1]), s2.y, t2.y), 0.f);
            o0.z = fmaxf(fmaf(lo32(acc[p][2]), s2.z, t2.z), 0.f);
            o0.w = fmaxf(fmaf(lo32(acc[p][3]), s2.w, t2.w), 0.f);
            o1.x = fmaxf(fmaf(hi32(acc[p][0]), s2.x, t2.x), 0.f);
            o1.y = fmaxf(fmaf(hi32(acc[p][1]), s2.y, t2.y), 0.f);
            o1.z = fmaxf(fmaf(hi32(acc[p][2]), s2.z, t2.z), 0.f);
            o1.w = fmaxf(fmaf(hi32(acc[p][3]), s2.w, t2.w), 0.f);
            *(float4*)&ob[(size_t)(2 * p) * NF]     = o0;
            *(float4*)&ob[(size_t)(2 * p + 1) * NF] = o1;
        }
    }
}

extern "C" void kernel_launch(void* const* d_in, const int* in_sizes, int n_in,
                              void* d_out, int out_size) {
    const float* x   = (const float*)d_in[0];
    const float* dwk = (const float*)d_in[1];
    const float* dwb = (const float*)d_in[2];
    const float* g1  = (const float*)d_in[3];
    const float* b1  = (const float*)d_in[4];
    const float* m1  = (const float*)d_in[5];
    const float* v1  = (const float*)d_in[6];
    const float* pw  = (const float*)d_in[7];
    const float* pb  = (const float*)d_in[8];
    const float* g2  = (const float*)d_in[9];
    const float* b2  = (const float*)d_in[10];
    const float* m2  = (const float*)d_in[11];
    const float* v2  = (const float*)d_in[12];
    float* out = (float*)d_out;

    dim3 grid(NB * ND * ND);   // 4608 blocks: one (b,d,h) row (48 w) each
    dim3 block(192);
    dwsep3d_fused_kernel<<<grid, block>>>(x, dwk, dwb, g1, b1, m1, v1,
                                          pw, pb, g2, b2, m2, v2, out);
}